// round 9
// baseline (speedup 1.0000x reference)
#include <cuda_runtime.h>

#define NBLOCKS 444
#define NTHREADS 128

__device__ double g_partials[NBLOCKS];
__device__ unsigned int g_ticket = 0;

__device__ __forceinline__ double warpReduceD(double v) {
    #pragma unroll
    for (int o = 16; o > 0; o >>= 1)
        v += __shfl_down_sync(0xffffffffu, v, o);
    return v;
}

// se3_log from rotation's (trace, vee) + translation -> xi[6]
__device__ __forceinline__ void se3_log_tv(float tr, float vx, float vy, float vz,
                                           float w0, float w1, float w2,
                                           float* xi) {
    float c = 0.5f * (tr - 1.0f);
    c = fminf(fmaxf(c, -1.0f + 1e-7f), 1.0f - 1e-7f);
    float th = acosf(c);
    // sin(acos(c)) = sqrt(1-c^2), exact for th in [0, pi]
    float s = sqrtf(fmaxf(1.0f - c * c, 1e-20f));
    float t2 = th * th;
    float rr = __fdividef(1.0f, 2.0f * s * t2);  // shared reciprocal
    float factor = th * t2 * rr;                 // th/(2s)
    float D = rr * (2.0f * s - (1.0f + c) * th); // 1/t2 - (1+c)/(2 th s)
    float px = factor * vx;
    float py = factor * vy;
    float pz = factor * vz;
    float pd = px * w0 + py * w1 + pz * w2;
    float cx = py * w2 - pz * w1;
    float cy = pz * w0 - px * w2;
    float cz = px * w1 - py * w0;
    xi[0] = w0 - 0.5f * cx + D * (px * pd - t2 * w0);
    xi[1] = w1 - 0.5f * cy + D * (py * pd - t2 * w1);
    xi[2] = w2 - 0.5f * cz + D * (pz * pd - t2 * w2);
    xi[3] = px;
    xi[4] = py;
    xi[5] = pz;
}

// Full per-row loss term: returns quad(g)-quad(s) = (g-s)^T P (g+s)
__device__ __forceinline__ float row_q(float2 a0, float2 a1, float2 a2,
                                       float4 q0, float4 q1, float4 q2,
                                       const float* __restrict__ sP) {
    float r0i = a0.x, r1i = a0.y, r2i = a1.x;   // rho_in
    float x = a1.y, y = a2.x, z = a2.y;         // phi_in

    // ---- se3_exp(input): one MUFU.RCP via shared denominator th^3 ----
    float t2 = x * x + y * y + z * z;
    bool small = t2 < 1e-8f;
    float t2s = small ? 1.0f : t2;
    float th = sqrtf(t2s);
    float s, co;
    __sincosf(th, &s, &co);
    float r3 = __fdividef(1.0f, t2s * th);      // 1/th^3
    float A  = small ? 1.0f - t2 * (1.0f / 6.0f)  : s * t2s * r3;
    float Bc = small ? 0.5f - t2 * (1.0f / 24.0f) : (1.0f - co) * th * r3;
    float Cc = small ? (1.0f / 6.0f) - t2 * (1.0f / 120.0f)
                     : (th - s) * r3;
    float R1[9];
    R1[0] = 1.0f + Bc * (x * x - t2);
    R1[1] = Bc * x * y - A * z;
    R1[2] = Bc * x * z + A * y;
    R1[3] = Bc * x * y + A * z;
    R1[4] = 1.0f + Bc * (y * y - t2);
    R1[5] = Bc * y * z - A * x;
    R1[6] = Bc * x * z - A * y;
    R1[7] = Bc * y * z + A * x;
    R1[8] = 1.0f + Bc * (z * z - t2);
    float pd = x * r0i + y * r1i + z * r2i;
    float cx = y * r2i - z * r1i;
    float cy = z * r0i - x * r2i;
    float cz = x * r1i - y * r0i;
    float t1x = r0i + Bc * cx + Cc * (x * pd - t2 * r0i);
    float t1y = r1i + Bc * cy + Cc * (y * pd - t2 * r1i);
    float t1z = r2i + Bc * cz + Cc * (z * pd - t2 * r2i);

    float Rt[9] = {q0.x, q0.y, q0.z, q1.x, q1.y, q1.z, q2.x, q2.y, q2.z};
    float tt0 = q0.w, tt1 = q1.w, tt2 = q2.w;

    // ---- M = R1 @ Rt, but only materialize trace + vee + tm ----
    float trM = 0.0f, mvx = 0.0f, mvy = 0.0f, mvz = 0.0f;
    #pragma unroll
    for (int k = 0; k < 3; k++) {
        float a0k = R1[0 * 3 + k], a1k = R1[1 * 3 + k], a2k = R1[2 * 3 + k];
        float bk0 = Rt[k * 3 + 0], bk1 = Rt[k * 3 + 1], bk2 = Rt[k * 3 + 2];
        trM = fmaf(a0k, bk0, fmaf(a1k, bk1, fmaf(a2k, bk2, trM)));
        mvx += a2k * bk1 - a1k * bk2;   // M[2,1]-M[1,2]
        mvy += a0k * bk2 - a2k * bk0;   // M[0,2]-M[2,0]
        mvz += a1k * bk0 - a0k * bk1;   // M[1,0]-M[0,1]
    }
    float tmx = R1[0] * tt0 + R1[1] * tt1 + R1[2] * tt2 + t1x;
    float tmy = R1[3] * tt0 + R1[4] * tt1 + R1[5] * tt2 + t1y;
    float tmz = R1[6] * tt0 + R1[7] * tt1 + R1[8] * tt2 + t1z;

    // ---- logs: trace/vee of Rt come straight from loads ----
    float xg[6], xs[6];
    se3_log_tv(trM, mvx, mvy, mvz, tmx, tmy, tmz, xg);
    se3_log_tv(q0.x + q1.y + q2.z,
               q2.y - q1.z, q0.z - q2.x, q1.x - q0.y,
               tt0, tt1, tt2, xs);

    float u[6], v[6];
    #pragma unroll
    for (int i = 0; i < 6; i++) { u[i] = xg[i] - xs[i]; v[i] = xg[i] + xs[i]; }
    float q = 0.0f;
    #pragma unroll
    for (int i = 0; i < 6; i++) {
        float w = 0.0f;
        #pragma unroll
        for (int j = 0; j < 6; j++)
            w = fmaf(sP[i * 6 + j], v[j], w);
        q = fmaf(u[i], w, q);
    }
    return q;
}

__global__ void __launch_bounds__(NTHREADS, 3)
se3_loss_main(const float* __restrict__ inp, const float* __restrict__ T,
              const float* __restrict__ P, float* __restrict__ out, int B) {
    __shared__ float sP[36];
    if (threadIdx.x < 36) sP[threadIdx.x] = P[threadIdx.x];
    __syncthreads();

    const int S = NBLOCKS * NTHREADS;
    int b = blockIdx.x * NTHREADS + threadIdx.x;
    double acc = 0.0;

    // ---- software-pipelined 2-row loop with validity masks ----
    bool v0 = b < B;
    bool v1 = b + S < B;
    int i0 = v0 ? b : 0;
    int i1 = v1 ? (b + S) : 0;
    // preload current pair
    const float2* ipa = (const float2*)(inp + 6 * i0);
    const float2* ipb = (const float2*)(inp + 6 * i1);
    const float4* Tpa = (const float4*)(T + 16 * i0);
    const float4* Tpb = (const float4*)(T + 16 * i1);
    float2 a0 = ipa[0], a1 = ipa[1], a2 = ipa[2];
    float2 c0 = ipb[0], c1 = ipb[1], c2 = ipb[2];
    float4 p0 = Tpa[0], p1 = Tpa[1], p2 = Tpa[2];
    float4 r0 = Tpb[0], r1 = Tpb[1], r2 = Tpb[2];

    while (v0) {
        int nb = b + 2 * S;
        bool nv0 = nb < B;
        bool nv1 = nb + S < B;
        int j0 = nv0 ? nb : 0;
        int j1 = nv1 ? (nb + S) : 0;
        // prefetch next pair (always executed; index 0 is safe)
        const float2* nipa = (const float2*)(inp + 6 * j0);
        const float2* nipb = (const float2*)(inp + 6 * j1);
        const float4* nTpa = (const float4*)(T + 16 * j0);
        const float4* nTpb = (const float4*)(T + 16 * j1);
        float2 e0 = nipa[0], e1 = nipa[1], e2 = nipa[2];
        float2 f0 = nipb[0], f1 = nipb[1], f2 = nipb[2];
        float4 g0 = nTpa[0], g1 = nTpa[1], g2 = nTpa[2];
        float4 h0 = nTpb[0], h1 = nTpb[1], h2 = nTpb[2];

        // compute on current pair (two independent chains)
        float qa = row_q(a0, a1, a2, p0, p1, p2, sP);
        float qb = row_q(c0, c1, c2, r0, r1, r2, sP);
        acc += (v0 ? (double)qa : 0.0) + (v1 ? (double)qb : 0.0);

        // rotate buffers
        a0 = e0; a1 = e1; a2 = e2;
        c0 = f0; c1 = f1; c2 = f2;
        p0 = g0; p1 = g1; p2 = g2;
        r0 = h0; r1 = h1; r2 = h2;
        b = nb; v0 = nv0; v1 = nv1;
    }

    // ---- block reduction ----
    acc = warpReduceD(acc);
    __shared__ double sw[NTHREADS / 32];
    if ((threadIdx.x & 31) == 0) sw[threadIdx.x >> 5] = acc;
    __syncthreads();
    __shared__ bool amLast;
    if (threadIdx.x < 32) {
        double v = (threadIdx.x < NTHREADS / 32) ? sw[threadIdx.x] : 0.0;
        v = warpReduceD(v);
        if (threadIdx.x == 0) {
            g_partials[blockIdx.x] = v;
            __threadfence();
            unsigned int t = atomicInc(&g_ticket, NBLOCKS - 1);  // self-resetting
            amLast = (t == NBLOCKS - 1);
        }
    }
    __syncthreads();

    // ---- last block reduces all partials (fixed order -> deterministic) ----
    if (amLast) {
        double v = 0.0;
        for (int i = threadIdx.x; i < NBLOCKS; i += NTHREADS)
            v += g_partials[i];
        v = warpReduceD(v);
        if ((threadIdx.x & 31) == 0) sw[threadIdx.x >> 5] = v;
        __syncthreads();
        if (threadIdx.x < 32) {
            double t = (threadIdx.x < NTHREADS / 32) ? sw[threadIdx.x] : 0.0;
            t = warpReduceD(t);
            if (threadIdx.x == 0)
                out[0] = (float)(0.5 / (double)B * t);
        }
    }
}

extern "C" void kernel_launch(void* const* d_in, const int* in_sizes, int n_in,
                              void* d_out, int out_size) {
    const float* inp = (const float*)d_in[0];        // (B, 6)
    const float* T   = (const float*)d_in[1];        // (B, 4, 4)
    const float* P   = (const float*)d_in[2];        // (6, 6)
    float* out = (float*)d_out;
    int B = in_sizes[0] / 6;
    se3_loss_main<<<NBLOCKS, NTHREADS>>>(inp, T, P, out, B);
}

// round 10
// speedup vs baseline: 1.1364x; 1.1364x over previous
#include <cuda_runtime.h>

#define NBLOCKS 296
#define NTHREADS 256

__device__ double g_partials[NBLOCKS];
__device__ unsigned int g_ticket = 0;

__device__ __forceinline__ double warpReduceD(double v) {
    #pragma unroll
    for (int o = 16; o > 0; o >>= 1)
        v += __shfl_down_sync(0xffffffffu, v, o);
    return v;
}

// se3_log from rotation's (trace, vee) + translation -> xi[6]
__device__ __forceinline__ void se3_log_tv(float tr, float vx, float vy, float vz,
                                           float w0, float w1, float w2,
                                           float* xi) {
    float c = 0.5f * (tr - 1.0f);
    c = fminf(fmaxf(c, -1.0f + 1e-7f), 1.0f - 1e-7f);
    float th = acosf(c);
    // sin(acos(c)) = sqrt(1-c^2), exact for th in [0, pi]
    float s = sqrtf(fmaxf(1.0f - c * c, 1e-20f));
    float t2 = th * th;
    float rr = __fdividef(1.0f, 2.0f * s * t2);  // shared reciprocal
    float factor = th * t2 * rr;                 // th/(2s)
    float D = rr * (2.0f * s - (1.0f + c) * th); // 1/t2 - (1+c)/(2 th s)
    float px = factor * vx;
    float py = factor * vy;
    float pz = factor * vz;
    float pd = px * w0 + py * w1 + pz * w2;
    float cx = py * w2 - pz * w1;
    float cy = pz * w0 - px * w2;
    float cz = px * w1 - py * w0;
    xi[0] = w0 - 0.5f * cx + D * (px * pd - t2 * w0);
    xi[1] = w1 - 0.5f * cy + D * (py * pd - t2 * w1);
    xi[2] = w2 - 0.5f * cz + D * (pz * pd - t2 * w2);
    xi[3] = px;
    xi[4] = py;
    xi[5] = pz;
}

// Full per-row loss term: returns quad(g)-quad(s) = (g-s)^T P (g+s)
__device__ __forceinline__ float row_q(float2 a0, float2 a1, float2 a2,
                                       float4 q0, float4 q1, float4 q2,
                                       const float* __restrict__ sP) {
    float r0i = a0.x, r1i = a0.y, r2i = a1.x;   // rho_in
    float x = a1.y, y = a2.x, z = a2.y;         // phi_in

    // ---- se3_exp(input): one MUFU.RCP via shared denominator th^3 ----
    float t2 = x * x + y * y + z * z;
    bool small = t2 < 1e-8f;
    float t2s = small ? 1.0f : t2;
    float th = sqrtf(t2s);
    float s, co;
    __sincosf(th, &s, &co);
    float r3 = __fdividef(1.0f, t2s * th);      // 1/th^3
    float A  = small ? 1.0f - t2 * (1.0f / 6.0f)  : s * t2s * r3;
    float Bc = small ? 0.5f - t2 * (1.0f / 24.0f) : (1.0f - co) * th * r3;
    float Cc = small ? (1.0f / 6.0f) - t2 * (1.0f / 120.0f)
                     : (th - s) * r3;
    float R1[9];
    R1[0] = 1.0f + Bc * (x * x - t2);
    R1[1] = Bc * x * y - A * z;
    R1[2] = Bc * x * z + A * y;
    R1[3] = Bc * x * y + A * z;
    R1[4] = 1.0f + Bc * (y * y - t2);
    R1[5] = Bc * y * z - A * x;
    R1[6] = Bc * x * z - A * y;
    R1[7] = Bc * y * z + A * x;
    R1[8] = 1.0f + Bc * (z * z - t2);
    float pd = x * r0i + y * r1i + z * r2i;
    float cx = y * r2i - z * r1i;
    float cy = z * r0i - x * r2i;
    float cz = x * r1i - y * r0i;
    float t1x = r0i + Bc * cx + Cc * (x * pd - t2 * r0i);
    float t1y = r1i + Bc * cy + Cc * (y * pd - t2 * r1i);
    float t1z = r2i + Bc * cz + Cc * (z * pd - t2 * r2i);

    float Rt[9] = {q0.x, q0.y, q0.z, q1.x, q1.y, q1.z, q2.x, q2.y, q2.z};
    float tt0 = q0.w, tt1 = q1.w, tt2 = q2.w;

    // ---- M = R1 @ Rt, but only materialize trace + vee + tm ----
    float trM = 0.0f, mvx = 0.0f, mvy = 0.0f, mvz = 0.0f;
    #pragma unroll
    for (int k = 0; k < 3; k++) {
        float a0k = R1[0 * 3 + k], a1k = R1[1 * 3 + k], a2k = R1[2 * 3 + k];
        float bk0 = Rt[k * 3 + 0], bk1 = Rt[k * 3 + 1], bk2 = Rt[k * 3 + 2];
        trM = fmaf(a0k, bk0, fmaf(a1k, bk1, fmaf(a2k, bk2, trM)));
        mvx += a2k * bk1 - a1k * bk2;   // M[2,1]-M[1,2]
        mvy += a0k * bk2 - a2k * bk0;   // M[0,2]-M[2,0]
        mvz += a1k * bk0 - a0k * bk1;   // M[1,0]-M[0,1]
    }
    float tmx = R1[0] * tt0 + R1[1] * tt1 + R1[2] * tt2 + t1x;
    float tmy = R1[3] * tt0 + R1[4] * tt1 + R1[5] * tt2 + t1y;
    float tmz = R1[6] * tt0 + R1[7] * tt1 + R1[8] * tt2 + t1z;

    // ---- logs: trace/vee of Rt come straight from loads ----
    float xg[6], xs[6];
    se3_log_tv(trM, mvx, mvy, mvz, tmx, tmy, tmz, xg);
    se3_log_tv(q0.x + q1.y + q2.z,
               q2.y - q1.z, q0.z - q2.x, q1.x - q0.y,
               tt0, tt1, tt2, xs);

    float u[6], v[6];
    #pragma unroll
    for (int i = 0; i < 6; i++) { u[i] = xg[i] - xs[i]; v[i] = xg[i] + xs[i]; }
    float q = 0.0f;
    #pragma unroll
    for (int i = 0; i < 6; i++) {
        float w = 0.0f;
        #pragma unroll
        for (int j = 0; j < 6; j++)
            w = fmaf(sP[i * 6 + j], v[j], w);
        q = fmaf(u[i], w, q);
    }
    return q;
}

__global__ void __launch_bounds__(NTHREADS, 2)
se3_loss_main(const float* __restrict__ inp, const float* __restrict__ T,
              const float* __restrict__ P, float* __restrict__ out, int B) {
    __shared__ float sP[36];
    if (threadIdx.x < 36) sP[threadIdx.x] = P[threadIdx.x];
    __syncthreads();

    const int S = NBLOCKS * NTHREADS;
    int b = blockIdx.x * NTHREADS + threadIdx.x;
    double acc = 0.0;

    // ---- preload inp for the first pair (chain-entry data) ----
    float2 a0, a1, a2, c0, c1, c2;
    {
        bool v0 = b < B, v1 = b + S < B;
        const float2* ipa = (const float2*)(inp + 6 * (v0 ? b : 0));
        const float2* ipb = (const float2*)(inp + 6 * (v1 ? (b + S) : 0));
        a0 = ipa[0]; a1 = ipa[1]; a2 = ipa[2];
        c0 = ipb[0]; c1 = ipb[1]; c2 = ipb[2];
    }

    int bb = b;
    for (; bb + S < B; bb += 2 * S) {
        int b1 = bb + S;
        // T loads for current pair (consumed mid-chain -> partially hidden)
        const float4* Tpa = (const float4*)(T + 16 * bb);
        const float4* Tpb = (const float4*)(T + 16 * b1);
        float4 p0 = Tpa[0], p1 = Tpa[1], p2 = Tpa[2];
        float4 r0 = Tpb[0], r1 = Tpb[1], r2 = Tpb[2];

        // prefetch next pair's inp (chain-entry data for next iteration)
        int nb = bb + 2 * S;
        bool nv0 = nb < B, nv1 = nb + S < B;
        const float2* nipa = (const float2*)(inp + 6 * (nv0 ? nb : 0));
        const float2* nipb = (const float2*)(inp + 6 * (nv1 ? (nb + S) : 0));
        float2 e0 = nipa[0], e1 = nipa[1], e2 = nipa[2];
        float2 f0 = nipb[0], f1 = nipb[1], f2 = nipb[2];

        // compute on current pair (two independent chains)
        float qa = row_q(a0, a1, a2, p0, p1, p2, sP);
        float qb = row_q(c0, c1, c2, r0, r1, r2, sP);
        acc += (double)qa + (double)qb;

        a0 = e0; a1 = e1; a2 = e2;
        c0 = f0; c1 = f1; c2 = f2;
    }
    // ---- tail: at most one row left (its inp is already in a0..a2) ----
    if (bb < B) {
        const float4* Tpa = (const float4*)(T + 16 * bb);
        float4 p0 = Tpa[0], p1 = Tpa[1], p2 = Tpa[2];
        acc += (double)row_q(a0, a1, a2, p0, p1, p2, sP);
    }

    // ---- block reduction ----
    acc = warpReduceD(acc);
    __shared__ double sw[NTHREADS / 32];
    if ((threadIdx.x & 31) == 0) sw[threadIdx.x >> 5] = acc;
    __syncthreads();
    __shared__ bool amLast;
    if (threadIdx.x < 32) {
        double v = (threadIdx.x < NTHREADS / 32) ? sw[threadIdx.x] : 0.0;
        v = warpReduceD(v);
        if (threadIdx.x == 0) {
            g_partials[blockIdx.x] = v;
            __threadfence();
            unsigned int t = atomicInc(&g_ticket, NBLOCKS - 1);  // self-resetting
            amLast = (t == NBLOCKS - 1);
        }
    }
    __syncthreads();

    // ---- last block reduces all partials (fixed order -> deterministic) ----
    if (amLast) {
        double v = 0.0;
        for (int i = threadIdx.x; i < NBLOCKS; i += NTHREADS)
            v += g_partials[i];
        v = warpReduceD(v);
        if ((threadIdx.x & 31) == 0) sw[threadIdx.x >> 5] = v;
        __syncthreads();
        if (threadIdx.x < 32) {
            double t = (threadIdx.x < NTHREADS / 32) ? sw[threadIdx.x] : 0.0;
            t = warpReduceD(t);
            if (threadIdx.x == 0)
                out[0] = (float)(0.5 / (double)B * t);
        }
    }
}

extern "C" void kernel_launch(void* const* d_in, const int* in_sizes, int n_in,
                              void* d_out, int out_size) {
    const float* inp = (const float*)d_in[0];        // (B, 6)
    const float* T   = (const float*)d_in[1];        // (B, 4, 4)
    const float* P   = (const float*)d_in[2];        // (6, 6)
    float* out = (float*)d_out;
    int B = in_sizes[0] / 6;
    se3_loss_main<<<NBLOCKS, NTHREADS>>>(inp, T, P, out, B);
}